// round 3
// baseline (speedup 1.0000x reference)
#include <cuda_runtime.h>

#define N_NODES 20000
#define N_EDGES 200000
#define D 32
#define R 100
#define EPS 1e-5f
#define MAXWL 8192
#define NB 400          // histogram/scatter blocks
#define EPB 500         // edges per block (NB*EPB == N_EDGES)

// ---------------- device scratch (static, no runtime allocation) --------
__device__ int   g_dcnt[N_NODES];           // per-dst edge counts
__device__ int   g_doff[N_NODES + 1];       // CSR offsets by dst
__device__ int   g_dcur[N_NODES];           // scatter cursors by dst
__device__ int   g_bh[R * NB];              // per-(relation, block) histogram
__device__ int   g_boff[R * NB];            // per-(relation, block) base offset
__device__ int   g_hist[R];                 // per-relation totals
__device__ int   g_off[R + 1];              // exclusive scan of g_hist
__device__ int   g_chunkbase[R + 1];
__device__ int   g_ssrc[N_EDGES];           // src sorted by etype
__device__ int   g_eidx2[N_EDGES];          // msg-positions grouped by dst
__device__ float g_msg[N_EDGES * D];        // relu(h[src] @ W[etype]), etype order
__device__ float g_sum[D], g_sumsq[D];
__device__ float g_scale[D], g_shift[D];
__device__ int   g_nchunk;
__device__ int   g_wl_r[MAXWL], g_wl_s[MAXWL], g_wl_n[MAXWL];

// ---------------- K0: zero per-call accumulators ----------------
__global__ void k0_zero() {
    int i = blockIdx.x * blockDim.x + threadIdx.x;
    int stride = gridDim.x * blockDim.x;
    for (int j = i; j < N_NODES; j += stride) g_dcnt[j] = 0;
    if (i < D) { g_sum[i] = 0.f; g_sumsq[i] = 0.f; }
}

// ---------------- K1: per-block etype histograms + global dst histogram --
__global__ void __launch_bounds__(256) k1_hist(const int* __restrict__ etype,
                                               const int* __restrict__ dst) {
    __shared__ int sh[R];
    for (int i = threadIdx.x; i < R; i += blockDim.x) sh[i] = 0;
    __syncthreads();
    int base = blockIdx.x * EPB;
    for (int i = threadIdx.x; i < EPB; i += blockDim.x) {
        atomicAdd(&sh[etype[base + i]], 1);
        atomicAdd(&g_dcnt[dst[base + i]], 1);   // 20K spread addrs: cheap
    }
    __syncthreads();
    for (int r = threadIdx.x; r < R; r += blockDim.x)
        g_bh[r * NB + blockIdx.x] = sh[r];
}

// ---------------- K2: etype 2D scan + worklist (single block) ------------
__global__ void __launch_bounds__(128) k2_scan() {
    int t = threadIdx.x;
    for (int r = t; r < R; r += blockDim.x) {
        int acc = 0;
#pragma unroll 8
        for (int b = 0; b < NB; b++) {
            g_boff[r * NB + b] = acc;
            acc += g_bh[r * NB + b];
        }
        g_hist[r] = acc;
    }
    __syncthreads();
    if (t == 0) {
        int acc = 0, cacc = 0;
        for (int r = 0; r < R; r++) {
            g_off[r] = acc;
            g_chunkbase[r] = cacc;
            acc += g_hist[r];
            cacc += (g_hist[r] + 31) / 32;
        }
        g_off[R] = acc;
        g_chunkbase[R] = cacc;
        g_nchunk = cacc;
    }
    __syncthreads();
    for (int r = t; r < R; r += blockDim.x) {
        int o = g_off[r];
#pragma unroll 8
        for (int b = 0; b < NB; b++) g_boff[r * NB + b] += o;
        int s = g_off[r], e2 = g_off[r + 1], w = g_chunkbase[r];
        for (int p = s; p < e2; p += 32) {
            g_wl_r[w] = r; g_wl_s[w] = p; g_wl_n[w] = min(32, e2 - p);
            w++;
        }
    }
}

// ---------------- K2b: dst-offset scan + cursor init (single block) ------
__global__ void __launch_bounds__(256) k2b_dscan() {
    __shared__ int part[256];
    int t = threadIdx.x;
    const int BPT = (N_NODES + 255) / 256;   // 79
    int lo = t * BPT, hi = min(lo + BPT, N_NODES);
    int lsum = 0;
    for (int i = lo; i < hi; i++) lsum += g_dcnt[i];
    part[t] = lsum;
    __syncthreads();
    if (t == 0) {
        int acc = 0;
        for (int i = 0; i < 256; i++) { int v = part[i]; part[i] = acc; acc += v; }
    }
    __syncthreads();
    int acc = part[t];
    for (int i = lo; i < hi; i++) {
        g_doff[i] = acc;
        g_dcur[i] = acc;
        acc += g_dcnt[i];
    }
    if (hi == N_NODES) g_doff[N_NODES] = acc;
}

// ---------------- K3: dual scatter (etype perm + dst perm) ----------------
__global__ void __launch_bounds__(256) k3_scatter(
    const int* __restrict__ etype, const int* __restrict__ src,
    const int* __restrict__ dst)
{
    __shared__ int cur[R];
    for (int r = threadIdx.x; r < R; r += blockDim.x)
        cur[r] = g_boff[r * NB + blockIdx.x];
    __syncthreads();
    int base = blockIdx.x * EPB;
    for (int i = threadIdx.x; i < EPB; i += blockDim.x) {
        int e = base + i;
        int pos = atomicAdd(&cur[etype[e]], 1);    // shared, low contention
        g_ssrc[pos] = src[e];
        int dpos = atomicAdd(&g_dcur[dst[e]], 1);  // 20K spread addrs
        g_eidx2[dpos] = pos;
    }
}

// ---------------- K4: GEMV pass — shared h-tile, LDS.128 broadcast --------
// One warp = one 32-edge chunk of a single relation. Lane d holds column d
// of W[r] in registers. h rows staged to shared; inner loop: 8 LDS.128
// broadcasts + 32 FMA per edge (no data shuffles).
__global__ void __launch_bounds__(128) k4_compute(
    const float* __restrict__ h, const float* __restrict__ weight)
{
    __shared__ float tile[4][32][32];   // [warp][edge][dim], rows 128B-aligned
    const int lane = threadIdx.x & 31;
    const int wid  = threadIdx.x >> 5;
    const int warp = (blockIdx.x * blockDim.x + threadIdx.x) >> 5;
    const int nwarp = (gridDim.x * blockDim.x) >> 5;
    const int nchunk = g_nchunk;

    float lsum = 0.f, lsq = 0.f;

    for (int w = warp; w < nchunk; w += nwarp) {
        int r = g_wl_r[w], s = g_wl_s[w], n = g_wl_n[w];
        const float* wp = weight + r * (D * D) + lane;
        float wc[32];
#pragma unroll
        for (int k = 0; k < 32; k++) wc[k] = wp[k * 32];

        int sj = 0;
        if (lane < n) sj = g_ssrc[s + lane];
        // stage h rows for this chunk's edges into shared (coalesced)
        for (int j = 0; j < n; j++) {
            int sje = __shfl_sync(0xffffffffu, sj, j);
            tile[wid][j][lane] = h[sje * D + lane];
        }
        __syncwarp();

        for (int j = 0; j < n; j++) {
            const float4* row = (const float4*)tile[wid][j];
            float a0 = 0.f, a1 = 0.f, a2 = 0.f, a3 = 0.f;
#pragma unroll
            for (int kk = 0; kk < 8; kk++) {
                float4 hq = row[kk];                 // 16B broadcast LDS
                a0 = fmaf(hq.x, wc[4 * kk + 0], a0);
                a1 = fmaf(hq.y, wc[4 * kk + 1], a1);
                a2 = fmaf(hq.z, wc[4 * kk + 2], a2);
                a3 = fmaf(hq.w, wc[4 * kk + 3], a3);
            }
            float acc = fmaxf((a0 + a1) + (a2 + a3), 0.f);
            lsum += acc;
            lsq = fmaf(acc, acc, lsq);
            g_msg[(s + j) * D + lane] = acc;         // coalesced 128B store
        }
        __syncwarp();
    }
    // block-level reduce, then one warp does the global atomics
    __shared__ float ssum[4][32], ssq[4][32];
    ssum[wid][lane] = lsum; ssq[wid][lane] = lsq;
    __syncthreads();
    if (wid == 0) {
        float ts = ssum[0][lane] + ssum[1][lane] + ssum[2][lane] + ssum[3][lane];
        float tq = ssq[0][lane] + ssq[1][lane] + ssq[2][lane] + ssq[3][lane];
        atomicAdd(&g_sum[lane], ts);
        atomicAdd(&g_sumsq[lane], tq);
    }
}

// ---------------- K5: fold batchnorm into affine scale/shift -------------
__global__ void k5_final(const float* __restrict__ gamma,
                         const float* __restrict__ beta) {
    int d = threadIdx.x;
    if (d < D) {
        float inv_e = 1.0f / (float)N_EDGES;
        float mu = g_sum[d] * inv_e;
        float var = fmaxf(g_sumsq[d] * inv_e - mu * mu, 0.f);
        float scale = rsqrtf(var + EPS) * gamma[d];
        g_scale[d] = scale;
        g_shift[d] = beta[d] - mu * scale;
    }
}

// ---------------- K6: warp-per-node gather reduce (atomic-free) ----------
// out[n] = (sc * sum(msg_e) + cnt*shf) / max(cnt,1); affine folded in.
__global__ void __launch_bounds__(128) k6_reduce(float* __restrict__ out) {
    const int lane = threadIdx.x & 31;
    const int node = (blockIdx.x * blockDim.x + threadIdx.x) >> 5;
    if (node >= N_NODES) return;
    const float sc = g_scale[lane], shf = g_shift[lane];

    int off = g_doff[node], end = g_doff[node + 1];
    int cnt = end - off;
    float acc = 0.f;
    int i = off;
    // 2-deep software pipeline on the index loads
    for (; i + 1 < end; i += 2) {
        int p0 = g_eidx2[i];
        int p1 = g_eidx2[i + 1];
        acc += g_msg[p0 * D + lane];
        acc += g_msg[p1 * D + lane];
    }
    if (i < end) acc += g_msg[g_eidx2[i] * D + lane];

    float v = 0.f;
    if (cnt > 0) v = fmaf(acc * (1.0f / (float)cnt), sc, shf);
    out[node * D + lane] = v;
}

extern "C" void kernel_launch(void* const* d_in, const int* in_sizes, int n_in,
                              void* d_out, int out_size) {
    const float* h      = (const float*)d_in[0];
    const float* weight = (const float*)d_in[1];
    const float* gamma  = (const float*)d_in[2];
    const float* beta   = (const float*)d_in[3];
    const int*   src    = (const int*)d_in[4];
    const int*   dst    = (const int*)d_in[5];
    const int*   etype  = (const int*)d_in[6];
    float* out = (float*)d_out;

    k0_zero<<<160, 128>>>();
    k1_hist<<<NB, 256>>>(etype, dst);
    k2_scan<<<1, 128>>>();
    k2b_dscan<<<1, 256>>>();
    k3_scatter<<<NB, 256>>>(etype, src, dst);
    k4_compute<<<1600, 128>>>(h, weight);
    k5_final<<<1, 32>>>(gamma, beta);
    k6_reduce<<<(N_NODES * 32 + 127) / 128, 128>>>(out);
}

// round 4
// speedup vs baseline: 2.2077x; 2.2077x over previous
#include <cuda_runtime.h>

#define N_NODES 20000
#define N_EDGES 200000
#define D 32
#define R 100
#define EPS 1e-5f
#define NB 400          // histogram/scatter blocks
#define EPB 500         // edges per block (NB*EPB == N_EDGES)
#define FULL 0xffffffffu

// ---------------- device scratch (static, no runtime allocation) --------
__device__ int   g_dcnt[N_NODES];           // per-dst edge counts
__device__ int   g_doff[N_NODES + 1];       // CSR offsets by dst
__device__ int   g_dcur[N_NODES];           // scatter cursors by dst
__device__ int   g_bh[R * NB];              // per-(relation, block) histogram
__device__ int   g_boff[R * NB];            // per-(relation, block) base offset
__device__ int   g_hist[R];                 // per-relation totals
__device__ int   g_off[R + 1];              // exclusive scan of g_hist
__device__ int   g_chunkbase[R + 1];        // exclusive scan of chunk counts
__device__ int   g_ssrc[N_EDGES];           // src sorted by etype
__device__ int   g_eidx2[N_EDGES];          // msg-positions grouped by dst
__device__ float g_msg[N_EDGES * D];        // relu(h[src] @ W[etype]), etype order
__device__ float g_sum[D], g_sumsq[D];
__device__ float g_scale[D], g_shift[D];
__device__ int   g_nchunk;

// ---------------- K0: zero per-call accumulators ----------------
__global__ void k0_zero() {
    int i = blockIdx.x * blockDim.x + threadIdx.x;
    int stride = gridDim.x * blockDim.x;
    for (int j = i; j < N_NODES; j += stride) g_dcnt[j] = 0;
    if (i < D) { g_sum[i] = 0.f; g_sumsq[i] = 0.f; }
}

// ---------------- K1: per-block etype histograms + global dst histogram --
__global__ void __launch_bounds__(256) k1_hist(const int* __restrict__ etype,
                                               const int* __restrict__ dst) {
    __shared__ int sh[R];
    for (int i = threadIdx.x; i < R; i += blockDim.x) sh[i] = 0;
    __syncthreads();
    int base = blockIdx.x * EPB;
    for (int i = threadIdx.x; i < EPB; i += blockDim.x) {
        atomicAdd(&sh[etype[base + i]], 1);
        atomicAdd(&g_dcnt[dst[base + i]], 1);   // 20K spread addrs: cheap
    }
    __syncthreads();
    for (int r = threadIdx.x; r < R; r += blockDim.x)
        g_bh[r * NB + blockIdx.x] = sh[r];
}

// ---------------- K2: etype scans, fully warp-parallel (1 block) ---------
__global__ void __launch_bounds__(1024) k2_scan() {
    const int lane = threadIdx.x & 31;
    const int wid  = threadIdx.x >> 5;   // 0..31

    // phase 1: per-relation totals (warp-per-relation coalesced reduce)
    for (int r = wid; r < R; r += 32) {
        int s = 0;
        for (int b = lane; b < NB; b += 32) s += g_bh[r * NB + b];
#pragma unroll
        for (int d = 16; d > 0; d >>= 1) s += __shfl_down_sync(FULL, s, d);
        if (lane == 0) g_hist[r] = s;
    }
    __syncthreads();

    // phase 2: scan relation totals + chunk counts (warp 0, shfl scans)
    if (wid == 0) {
        int acc = 0, cacc = 0;
        for (int base = 0; base < R; base += 32) {
            int r = base + lane;
            int hv = (r < R) ? g_hist[r] : 0;
            int cv = (hv + 31) >> 5;
            int hs = hv, cs = cv;
#pragma unroll
            for (int d = 1; d < 32; d <<= 1) {
                int t1 = __shfl_up_sync(FULL, hs, d);
                int t2 = __shfl_up_sync(FULL, cs, d);
                if (lane >= d) { hs += t1; cs += t2; }
            }
            if (r < R) {
                g_off[r] = acc + hs - hv;
                g_chunkbase[r] = cacc + cs - cv;
            }
            acc  += __shfl_sync(FULL, hs, 31);
            cacc += __shfl_sync(FULL, cs, 31);
        }
        if (lane == 0) { g_off[R] = acc; g_chunkbase[R] = cacc; g_nchunk = cacc; }
    }
    __syncthreads();

    // phase 3: per-relation scan over blocks (warp-per-relation, shfl scan)
    for (int r = wid; r < R; r += 32) {
        int carry = g_off[r];
        for (int b0 = 0; b0 < NB; b0 += 32) {
            int b = b0 + lane;
            int v = (b < NB) ? g_bh[r * NB + b] : 0;
            int s = v;
#pragma unroll
            for (int d = 1; d < 32; d <<= 1) {
                int t = __shfl_up_sync(FULL, s, d);
                if (lane >= d) s += t;
            }
            if (b < NB) g_boff[r * NB + b] = carry + s - v;
            carry += __shfl_sync(FULL, s, 31);
        }
    }
}

// ---------------- K2b: dst-offset scan, warp-parallel (1 block) ----------
__global__ void __launch_bounds__(1024) k2b_dscan() {
    __shared__ int wsum[32], wbase[32];
    const int lane = threadIdx.x & 31;
    const int wid  = threadIdx.x >> 5;
    const int SEG = (N_NODES + 31) / 32;   // 625
    int lo = wid * SEG, hi = min(lo + SEG, N_NODES);

    int carry = 0;
    for (int i0 = lo; i0 < hi; i0 += 32) {
        int i = i0 + lane;
        int v = (i < hi) ? g_dcnt[i] : 0;
        int s = v;
#pragma unroll
        for (int d = 1; d < 32; d <<= 1) {
            int t = __shfl_up_sync(FULL, s, d);
            if (lane >= d) s += t;
        }
        if (i < hi) g_doff[i] = carry + s - v;     // local exclusive scan
        carry += __shfl_sync(FULL, s, 31);
    }
    if (lane == 0) wsum[wid] = carry;
    __syncthreads();
    if (wid == 0) {
        int v = wsum[lane];
        int s = v;
#pragma unroll
        for (int d = 1; d < 32; d <<= 1) {
            int t = __shfl_up_sync(FULL, s, d);
            if (lane >= d) s += t;
        }
        wbase[lane] = s - v;
        if (lane == 31) g_doff[N_NODES] = s;       // grand total
    }
    __syncthreads();
    int base = wbase[wid];
    for (int i = lo + lane; i < hi; i += 32) {
        int o = g_doff[i] + base;
        g_doff[i] = o;
        g_dcur[i] = o;
    }
}

// ---------------- K3: dual scatter (etype perm + dst perm) ----------------
__global__ void __launch_bounds__(256) k3_scatter(
    const int* __restrict__ etype, const int* __restrict__ src,
    const int* __restrict__ dst)
{
    __shared__ int cur[R];
    for (int r = threadIdx.x; r < R; r += blockDim.x)
        cur[r] = g_boff[r * NB + blockIdx.x];
    __syncthreads();
    int base = blockIdx.x * EPB;
    for (int i = threadIdx.x; i < EPB; i += blockDim.x) {
        int e = base + i;
        int pos = atomicAdd(&cur[etype[e]], 1);    // shared, low contention
        g_ssrc[pos] = src[e];
        int dpos = atomicAdd(&g_dcur[dst[e]], 1);  // 20K spread addrs
        g_eidx2[dpos] = pos;
    }
}

// ---------------- K4: GEMV pass — shared h-tile, LDS.128 broadcast --------
// One warp = one 32-edge chunk of one relation (found by binary search in
// shared chunkbase table). Lane d holds column d of W[r] in registers.
__global__ void __launch_bounds__(128) k4_compute(
    const float* __restrict__ h, const float* __restrict__ weight)
{
    __shared__ float tile[4][32][32];
    __shared__ int s_cb[R + 1], s_off[R + 1];
    const int lane = threadIdx.x & 31;
    const int wid  = threadIdx.x >> 5;
    const int warp = (blockIdx.x * blockDim.x + threadIdx.x) >> 5;
    const int nwarp = (gridDim.x * blockDim.x) >> 5;

    for (int i = threadIdx.x; i <= R; i += blockDim.x) {
        s_cb[i] = g_chunkbase[i];
        s_off[i] = g_off[i];
    }
    __syncthreads();
    const int nchunk = g_nchunk;

    float lsum = 0.f, lsq = 0.f;

    for (int w = warp; w < nchunk; w += nwarp) {
        // largest r with chunkbase[r] <= w
        int lo2 = 0, hi2 = R;
        while (lo2 < hi2) {
            int mid = (lo2 + hi2 + 1) >> 1;
            if (s_cb[mid] <= w) lo2 = mid; else hi2 = mid - 1;
        }
        int r = lo2;
        int s = s_off[r] + ((w - s_cb[r]) << 5);
        int n = min(32, s_off[r + 1] - s);

        const float* wp = weight + r * (D * D) + lane;
        float wc[32];
#pragma unroll
        for (int k = 0; k < 32; k++) wc[k] = wp[k * 32];

        int sj = 0;
        if (lane < n) sj = g_ssrc[s + lane];
        for (int j = 0; j < n; j++) {
            int sje = __shfl_sync(FULL, sj, j);
            tile[wid][j][lane] = h[sje * D + lane];   // coalesced 128B
        }
        __syncwarp();

        for (int j = 0; j < n; j++) {
            const float4* row = (const float4*)tile[wid][j];
            float a0 = 0.f, a1 = 0.f, a2 = 0.f, a3 = 0.f;
#pragma unroll
            for (int kk = 0; kk < 8; kk++) {
                float4 hq = row[kk];                  // 16B broadcast LDS
                a0 = fmaf(hq.x, wc[4 * kk + 0], a0);
                a1 = fmaf(hq.y, wc[4 * kk + 1], a1);
                a2 = fmaf(hq.z, wc[4 * kk + 2], a2);
                a3 = fmaf(hq.w, wc[4 * kk + 3], a3);
            }
            float acc = fmaxf((a0 + a1) + (a2 + a3), 0.f);
            lsum += acc;
            lsq = fmaf(acc, acc, lsq);
            g_msg[(s + j) * D + lane] = acc;          // coalesced 128B store
        }
        __syncwarp();
    }
    __shared__ float ssum[4][32], ssq[4][32];
    ssum[wid][lane] = lsum; ssq[wid][lane] = lsq;
    __syncthreads();
    if (wid == 0) {
        float ts = ssum[0][lane] + ssum[1][lane] + ssum[2][lane] + ssum[3][lane];
        float tq = ssq[0][lane] + ssq[1][lane] + ssq[2][lane] + ssq[3][lane];
        atomicAdd(&g_sum[lane], ts);
        atomicAdd(&g_sumsq[lane], tq);
    }
}

// ---------------- K5: fold batchnorm into affine scale/shift -------------
__global__ void k5_final(const float* __restrict__ gamma,
                         const float* __restrict__ beta) {
    int d = threadIdx.x;
    if (d < D) {
        float inv_e = 1.0f / (float)N_EDGES;
        float mu = g_sum[d] * inv_e;
        float var = fmaxf(g_sumsq[d] * inv_e - mu * mu, 0.f);
        float scale = rsqrtf(var + EPS) * gamma[d];
        g_scale[d] = scale;
        g_shift[d] = beta[d] - mu * scale;
    }
}

// ---------------- K6: warp-per-node gather reduce (atomic-free) ----------
__global__ void __launch_bounds__(128) k6_reduce(float* __restrict__ out) {
    const int lane = threadIdx.x & 31;
    const int node = (blockIdx.x * blockDim.x + threadIdx.x) >> 5;
    if (node >= N_NODES) return;
    const float sc = g_scale[lane], shf = g_shift[lane];

    int off = g_doff[node], end = g_doff[node + 1];
    int cnt = end - off;
    float acc = 0.f;
    int i = off;
    for (; i + 1 < end; i += 2) {
        int p0 = g_eidx2[i];
        int p1 = g_eidx2[i + 1];
        acc += g_msg[p0 * D + lane];
        acc += g_msg[p1 * D + lane];
    }
    if (i < end) acc += g_msg[g_eidx2[i] * D + lane];

    float v = 0.f;
    if (cnt > 0) v = fmaf(acc * (1.0f / (float)cnt), sc, shf);
    out[node * D + lane] = v;
}

extern "C" void kernel_launch(void* const* d_in, const int* in_sizes, int n_in,
                              void* d_out, int out_size) {
    const float* h      = (const float*)d_in[0];
    const float* weight = (const float*)d_in[1];
    const float* gamma  = (const float*)d_in[2];
    const float* beta   = (const float*)d_in[3];
    const int*   src    = (const int*)d_in[4];
    const int*   dst    = (const int*)d_in[5];
    const int*   etype  = (const int*)d_in[6];
    float* out = (float*)d_out;

    k0_zero<<<160, 128>>>();
    k1_hist<<<NB, 256>>>(etype, dst);
    k2_scan<<<1, 1024>>>();
    k2b_dscan<<<1, 1024>>>();
    k3_scatter<<<NB, 256>>>(etype, src, dst);
    k4_compute<<<1600, 128>>>(h, weight);
    k5_final<<<1, 32>>>(gamma, beta);
    k6_reduce<<<(N_NODES * 32 + 127) / 128, 128>>>(out);
}